// round 8
// baseline (speedup 1.0000x reference)
#include <cuda_runtime.h>
#include <cuda_fp16.h>

#define H_IMG 1080
#define W_IMG 1920
#define GY 16
#define GX 16
#define GW 8
#define NPIX (H_IMG * W_IMG)

#define BX 384                  // threads = output float4s per block
#define PXB (BX / 3)            // 128 pixels per block
#define BLK_PER_ROW (W_IMG / PXB)  // 15
#define NC 3                    // x-cells per 128-px strip
#define NCELL (NC * GW)         // 24

#define SX (15.0f / 1919.0f)
#define SY (15.0f / 1079.0f)

__device__ __forceinline__ float2 h2f(unsigned u) {
    __half2 h;
    *reinterpret_cast<unsigned*>(&h) = u;
    return __half22float2(h);
}

__global__ __launch_bounds__(BX) void bilateral_grid_kernel(
    const float* __restrict__ rgb,
    const float* __restrict__ grids,
    const int*   __restrict__ idxp,
    float*       __restrict__ out)
{
    // fp16 y-lerped slab: (cell, chunk) -> uint2 (4 halves). 72 uint2 = 576B
    __shared__ __align__(16) uint2 slab[NCELL * 3];

    const int tid   = threadIdx.x;
    const int row   = blockIdx.y;
    const int xpix0 = blockIdx.x * PXB;

    // thread's output element
    const int q = tid / 3;          // local pixel 0..127
    const int c = tid - 3 * q;      // chunk 0..2

    // ---- prefetch rgb for this thread's pixel (broadcast across 3 lanes) ----
    const int n = row * W_IMG + xpix0 + q;
    float r = __ldcs(rgb + n);
    float g = __ldcs(rgb + NPIX + n);
    float b = __ldcs(rgb + 2 * NPIX + n);

    // ---- block-uniform y lerp ----
    float gyv = (float)row * SY;
    float fy  = floorf(gyv);
    float wy  = gyv - fy;
    int y0 = min((int)fy, GY - 1);
    int y1 = min(y0 + 1, GY - 1);
    float wy0 = 1.0f - wy, wy1 = wy;

    const float* grid = grids + (size_t)idxp[0] * (GY * GX * GW * 12);
    int xbase = (int)((float)xpix0 * SX);

    // ---- build slab: 72 items (cell, chunk4) ----
    if (tid < NCELL * 3) {
        int cell = tid / 3;
        int c4   = tid - cell * 3;
        int xq   = cell / GW;
        int zq   = cell - xq * GW;
        int xc   = min(xbase + xq, GX - 1);
        float4 a = __ldg(reinterpret_cast<const float4*>(
            grid + ((size_t)(y0 * GX + xc) * GW + zq) * 12) + c4);
        float4 bb = __ldg(reinterpret_cast<const float4*>(
            grid + ((size_t)(y1 * GX + xc) * GW + zq) * 12) + c4);
        float4 o;
        o.x = wy0 * a.x + wy1 * bb.x;
        o.y = wy0 * a.y + wy1 * bb.y;
        o.z = wy0 * a.z + wy1 * bb.z;
        o.w = wy0 * a.w + wy1 * bb.w;
        __half2 h0 = __floats2half2_rn(o.x, o.y);
        __half2 h1 = __floats2half2_rn(o.z, o.w);
        uint2 pk;
        pk.x = *reinterpret_cast<unsigned*>(&h0);
        pk.y = *reinterpret_cast<unsigned*>(&h1);
        slab[tid] = pk;
    }
    __syncthreads();

    // ---- per-output-element work ----
    float gray = 0.299f * r + 0.587f * g + 0.114f * b;

    const int x = xpix0 + q;
    float gxv = (float)x * SX;
    float fx  = floorf(gxv);
    float wx  = gxv - fx;
    int xc0 = min((int)fx, GX - 1);
    int xc1 = min(xc0 + 1, GX - 1);
    int x0l = xc0 - xbase;
    int x1l = xc1 - xbase;

    float gz = __saturatef(gray) * (float)(GW - 1);
    float fz = floorf(gz);
    float wz = gz - fz;
    int z0 = min(max((int)fz, 0), GW - 1);
    int z1 = min(z0 + 1, GW - 1);

    float w00 = (1.0f - wx) * (1.0f - wz);
    float w01 = (1.0f - wx) * wz;
    float w10 = wx * (1.0f - wz);
    float w11 = wx * wz;

    // 4 corner chunk reads: LDS.64 each
    uint2 u00 = slab[(x0l * GW + z0) * 3 + c];
    uint2 u01 = slab[(x0l * GW + z1) * 3 + c];
    uint2 u10 = slab[(x1l * GW + z0) * 3 + c];
    uint2 u11 = slab[(x1l * GW + z1) * 3 + c];

    float4 a4;
    {
        float2 f0, f1;
        f0 = h2f(u00.x); f1 = h2f(u00.y);
        a4.x = w00 * f0.x; a4.y = w00 * f0.y; a4.z = w00 * f1.x; a4.w = w00 * f1.y;
        f0 = h2f(u01.x); f1 = h2f(u01.y);
        a4.x += w01 * f0.x; a4.y += w01 * f0.y; a4.z += w01 * f1.x; a4.w += w01 * f1.y;
        f0 = h2f(u10.x); f1 = h2f(u10.y);
        a4.x += w10 * f0.x; a4.y += w10 * f0.y; a4.z += w10 * f1.x; a4.w += w10 * f1.y;
        f0 = h2f(u11.x); f1 = h2f(u11.y);
        a4.x += w11 * f0.x; a4.y += w11 * f0.y; a4.z += w11 * f1.x; a4.w += w11 * f1.y;
    }

    const size_t base3 = (size_t)(row * W_IMG + xpix0) * 3;

    // affine: dense float4 store (warp writes 512B contiguous)
    __stcs(reinterpret_cast<float4*>(out) + base3 + tid, a4);

    // res: dense scalar store (warp writes 128B contiguous)
    float resv = a4.x * r + a4.y * g + a4.z * b + a4.w;
    __stcs(out + (size_t)12 * NPIX + base3 + tid, resv);
}

extern "C" void kernel_launch(void* const* d_in, const int* in_sizes, int n_in,
                              void* d_out, int out_size) {
    const float* rgb   = (const float*)d_in[0];
    const float* grids = (const float*)d_in[1];
    const int*   idx   = (const int*)d_in[2];
    float* out = (float*)d_out;

    dim3 grid(BLK_PER_ROW, H_IMG);   // 15 x 1080
    bilateral_grid_kernel<<<grid, BX>>>(rgb, grids, idx, out);
}